// round 8
// baseline (speedup 1.0000x reference)
#include <cuda_runtime.h>
#include <cstdint>

#define TT 2048
#define UNR 8

__device__ __forceinline__ float ex2_ap (float x){ float r; asm("ex2.approx.f32 %0, %1;"   : "=f"(r) : "f"(x)); return r; }
__device__ __forceinline__ float rcp_ap (float x){ float r; asm("rcp.approx.f32 %0, %1;"   : "=f"(r) : "f"(x)); return r; }
__device__ __forceinline__ float sqrt_ap(float x){ float r; asm("sqrt.approx.f32 %0, %1;"  : "=f"(r) : "f"(x)); return r; }
__device__ __forceinline__ float rsq_ap (float x){ float r; asm("rsqrt.approx.f32 %0, %1;" : "=f"(r) : "f"(x)); return r; }
__device__ __forceinline__ float clampf(float x, float lo, float hi){ return fminf(fmaxf(x, lo), hi); }
__device__ __forceinline__ float relu(float x){ return fmaxf(x, 0.f); }

struct Consts {
  float insc, Sc, Sinv, kexp, lCc, sub, crak, rk, lg, kr, ls;
};

// Full pass-2 Q for t==0: rolled SMS/GW = FINAL states, RS = outs[b,0,2]
__device__ __forceinline__ float q_final(float4 v, float SMS1r, float GW1r, float RSr, const Consts& c)
{
  float Prec = v.x, PET = v.y, RSmax = v.z, Area = v.w;
  float INTC = fminf(fminf(c.insc, PET), Prec);
  float INR  = Prec - INTC;
  float SMS1c = fmaxf(fminf(SMS1r, c.Sc), 0.f);
  float infil = ex2_ap(fmaf(c.kexp, SMS1c, c.lCc));
  float RMO = fminf(INR, infil);
  float IRUN = INR - RMO;
  float ratio = SMS1c * c.Sinv;
  float SRUN = c.sub * ratio * RMO;
  float BAS = c.rk * relu(GW1r);
  float inflow = (IRUN + SRUN + BAS) * Area;
  float x5 = RSr + inflow - RSmax;
  float Qor = relu(x5);
  float r = relu(RSr) * rcp_ap(RSmax);
  float pw = r * sqrt_ap(r);
  float Qir = (x5 > 0.f) ? (c.kr * RSmax) : (c.kr * RSr * pw);
  float drarg = (SRUN + IRUN) * (1.f - Area) + Qir + Qor - c.ls;
  float DR = relu(drarg);
  float GD = BAS * (1.f - Area);
  return relu(DR + GD);
}

// One fused step: scan update + pass-2 Q (valid t>=1; t==0 patched later).
// Carries sqrt(RS) as extra state so its latency hides under the next spine.
__device__ __forceinline__ float step(float4 v, float& S, float& G, float& R, float& sqR,
                                      const Consts& c)
{
  float Prec = v.x, PET = v.y, RSmax = v.z, Area = v.w;

  // input-only (off all chains)
  float INTC = fminf(fminf(c.insc, PET), Prec);
  float INR  = Prec - INTC;
  float POT  = PET  - INTC;
  float u    = rsq_ap(RSmax);
  float crs  = c.kr * (u * u * u);      // kr * RSmax^{-1.5}
  float krR  = c.kr * RSmax;
  float RSov = RSmax - krR;             // RSmax*(1-kr): RSn in overflow case
  float onemA = 1.f - Area;

  // ---- SMS spine: min(S,Sc) -> fma -> ex2 -> fma -> min ----
  float SMS1c = fminf(S, c.Sc);                 // >=0 invariant (proven)
  float infil = ex2_ap(fmaf(c.kexp, SMS1c, c.lCc));
  float ratio = SMS1c * c.Sinv;                 // side chain, ready before ex2
  float sr  = c.sub  * ratio;
  float cr  = c.crak * ratio;
  float msr = 1.f - sr;
  float m   = msr * (1.f - cr);
  float mcr = cr * msr;
  float ETS  = fminf(POT, 10.f * ratio);
  float base = SMS1c - ETS;
  float w = fmaf(m, INR,   base);
  float z = fmaf(m, infil, base);
  float SMSn = fminf(w, z);                     // == base + m*min(INR,infil) exactly

  // off-spine
  float RMO  = fminf(INR, infil);
  float U    = fmaf(-msr, RMO, INR);            // IRUN + SRUN
  float REC  = mcr * RMO;
  float RECn = REC + relu(SMSn - c.Sc);

  // GW (short chain)
  float reluG = relu(G);
  float BAS = c.rk * reluG;
  float GWn = ((G - c.lg) + RECn) - BAS;

  // RS (short chain; sqrt(R) carried from previous step)
  float inflow = (U + BAS) * Area;
  float Rpi = R + inflow;
  float x5  = Rpi - RSmax;
  float t1  = (crs * sqR) * R;                  // kr * R^1.5 / RSmax^1.5
  float RSn_no = fmaf(-t1, R, Rpi);             // R + inflow - kr*R*(R/RSmax)^1.5
  float RSn = (x5 > 0.f) ? RSov : RSn_no;
  float sqn = sqrt_ap(RSn);                     // for next step + q_out (RSn>=0 proven)

  // pass-2 Q with POST-step RS (zero extra MUFUs)
  float x6 = RSn + inflow - RSmax;
  float Qor2 = relu(x6);
  float Qir2 = (x6 > 0.f) ? krR : ((crs * RSn) * (RSn * sqn));  // kr*RSn*(RSn/RSmax)^1.5
  float drarg = fmaf(U, onemA, (Qir2 + Qor2) - c.ls);
  float Q = relu(relu(drarg) + BAS * onemA);

  S = SMSn; G = GWn; R = RSn; sqR = sqn;
  return Q;
}

__global__ void __launch_bounds__(256, 1)
hirnn_kernel(const float4* __restrict__ xin_all,
             const float* __restrict__ pINSC, const float* __restrict__ pCOEFF,
             const float* __restrict__ pSQ,   const float* __restrict__ pSMSC,
             const float* __restrict__ pSUB,  const float* __restrict__ pCRAK,
             const float* __restrict__ pRecK, const float* __restrict__ pKr,
             const float* __restrict__ pLG,   const float* __restrict__ pLS,
             float* __restrict__ out, int B)
{
  int b = blockIdx.x * 256 + threadIdx.x;
  if (b >= B) return;

  Consts c;
  c.insc = clampf(pINSC[0] * 5.f, 0.5f, 5.f);
  float Cc = clampf(pCOEFF[0] * 400.f, 50.f, 400.f);
  float qv = clampf(pSQ[0] * 6.f, 0.f, 6.f);
  c.Sc   = clampf(pSMSC[0] * 500.f, 50.f, 500.f);
  c.Sinv = 1.f / c.Sc;
  c.kexp = -qv * c.Sinv * 1.4426950408889634f;   // exp(-q*s/S)*Cc == exp2(kexp*s + lCc)
  c.lCc  = log2f(Cc);
  c.sub  = clampf(pSUB[0], 0.f, 1.f);
  c.crak = clampf(pCRAK[0], 0.f, 1.f);
  c.rk   = clampf(pRecK[0] * 0.3f, 0.003f, 0.3f);
  c.lg   = clampf(pLG[0] * 0.1f, 0.001f, 0.1f);
  c.kr   = clampf(pKr[0] * 0.1f, 0.01f, 0.1f);
  c.ls   = clampf(pLS[0] * 10.f, 0.01f, 10.f);

  const float4* __restrict__ xin = xin_all + (size_t)b * TT;
  float* __restrict__ op = out + (size_t)b * TT;

  float S = 0.f, G = 0.f, R = 0.f, sqR = 0.f;
  float rs0 = 0.f;

  float4 bufA[UNR], bufB[UNR];
#pragma unroll
  for (int i = 0; i < UNR; i++) bufA[i] = xin[i];
  float4 first = bufA[0];

  float qb0 = 0.f, qb1 = 0.f, qb2 = 0.f, qb3 = 0.f;

  for (int g = 0; g < TT; g += 2 * UNR) {
    // phase A: prefetch [g+8,g+16) into bufB, compute bufA
#pragma unroll
    for (int i = 0; i < UNR; i++) bufB[i] = xin[g + UNR + i];
#pragma unroll
    for (int i = 0; i < UNR; i++) {
      float Q = step(bufA[i], S, G, R, sqR, c);
      if (g + i == 0) rs0 = R;
      if      ((i & 3) == 0) qb0 = Q;
      else if ((i & 3) == 1) qb1 = Q;
      else if ((i & 3) == 2) qb2 = Q;
      else {
        qb3 = Q;
        *reinterpret_cast<float4*>(op + g + (i - 3)) = make_float4(qb0, qb1, qb2, qb3);
      }
    }
    // phase B: prefetch [g+16,g+24) into bufA, compute bufB
    if (g + 2 * UNR < TT) {
#pragma unroll
      for (int i = 0; i < UNR; i++) bufA[i] = xin[g + 2 * UNR + i];
    }
#pragma unroll
    for (int i = 0; i < UNR; i++) {
      float Q = step(bufB[i], S, G, R, sqR, c);
      if      ((i & 3) == 0) qb0 = Q;
      else if ((i & 3) == 1) qb1 = Q;
      else if ((i & 3) == 2) qb2 = Q;
      else {
        qb3 = Q;
        *reinterpret_cast<float4*>(op + g + UNR + (i - 3)) = make_float4(qb0, qb1, qb2, qb3);
      }
    }
  }

  // Q[b,0]: jnp.roll wrap -> SMS1/GW1 = FINAL states; RS = outs[b,0,2]
  op[0] = q_final(first, S, G, rs0, c);
}

extern "C" void kernel_launch(void* const* d_in, const int* in_sizes, int n_in,
                              void* d_out, int out_size) {
  const float4* xin = (const float4*)d_in[0];
  int B = out_size / TT;
  int grid = (B + 255) / 256;
  hirnn_kernel<<<grid, 256>>>(xin,
      (const float*)d_in[1], (const float*)d_in[2], (const float*)d_in[3],
      (const float*)d_in[4], (const float*)d_in[5], (const float*)d_in[6],
      (const float*)d_in[7], (const float*)d_in[8], (const float*)d_in[9],
      (const float*)d_in[10],
      (float*)d_out, B);
}

// round 9
// speedup vs baseline: 1.3419x; 1.3419x over previous
#include <cuda_runtime.h>
#include <cstdint>

#define TT 2048
#define CH 32
#define NCH (TT / CH)

__device__ __forceinline__ float ex2_ap (float x){ float r; asm("ex2.approx.f32 %0, %1;"   : "=f"(r) : "f"(x)); return r; }
__device__ __forceinline__ float rcp_ap (float x){ float r; asm("rcp.approx.f32 %0, %1;"   : "=f"(r) : "f"(x)); return r; }
__device__ __forceinline__ float sqrt_ap(float x){ float r; asm("sqrt.approx.f32 %0, %1;"  : "=f"(r) : "f"(x)); return r; }
__device__ __forceinline__ float rsq_ap (float x){ float r; asm("rsqrt.approx.f32 %0, %1;" : "=f"(r) : "f"(x)); return r; }
__device__ __forceinline__ float clampf(float x, float lo, float hi){ return fminf(fmaxf(x, lo), hi); }
__device__ __forceinline__ float relu(float x){ return fmaxf(x, 0.f); }

struct Consts {
  float insc, Sc, Sinv, kexp, lCc, sub, crak, rk, lg, kr, ls;
};

// Full pass-2 Q for t==0: rolled SMS/GW = FINAL states, RS = outs[b,0,2]
__device__ __forceinline__ float q_final(float4 v, float SMS1r, float GW1r, float RSr, const Consts& c)
{
  float Prec = v.x, PET = v.y, RSmax = v.z, Area = v.w;
  float INTC = fminf(fminf(c.insc, PET), Prec);
  float INR  = Prec - INTC;
  float SMS1c = fmaxf(fminf(SMS1r, c.Sc), 0.f);
  float infil = ex2_ap(fmaf(c.kexp, SMS1c, c.lCc));
  float RMO = fminf(INR, infil);
  float IRUN = INR - RMO;
  float ratio = SMS1c * c.Sinv;
  float SRUN = c.sub * ratio * RMO;
  float BAS = c.rk * relu(GW1r);
  float inflow = (IRUN + SRUN + BAS) * Area;
  float x5 = RSr + inflow - RSmax;
  float Qor = relu(x5);
  float r = relu(RSr) * rcp_ap(RSmax);
  float pw = r * sqrt_ap(r);
  float Qir = (x5 > 0.f) ? (c.kr * RSmax) : (c.kr * RSr * pw);
  float drarg = (SRUN + IRUN) * (1.f - Area) + Qir + Qor - c.ls;
  float DR = relu(drarg);
  float GD = BAS * (1.f - Area);
  return relu(DR + GD);
}

__global__ void __launch_bounds__(64, 1)
hirnn_kernel(const float4* __restrict__ xin_all,
             const float* __restrict__ pINSC, const float* __restrict__ pCOEFF,
             const float* __restrict__ pSQ,   const float* __restrict__ pSMSC,
             const float* __restrict__ pSUB,  const float* __restrict__ pCRAK,
             const float* __restrict__ pRecK, const float* __restrict__ pKr,
             const float* __restrict__ pLG,   const float* __restrict__ pLS,
             float* __restrict__ out, int B)
{
  const int lane = threadIdx.x & 31;
  const int warp = threadIdx.x >> 5;
  const int seq  = blockIdx.x * 32 + lane;

  Consts c;
  c.insc = clampf(pINSC[0] * 5.f, 0.5f, 5.f);
  float Cc = clampf(pCOEFF[0] * 400.f, 50.f, 400.f);
  float qv = clampf(pSQ[0] * 6.f, 0.f, 6.f);
  c.Sc   = clampf(pSMSC[0] * 500.f, 50.f, 500.f);
  c.Sinv = 1.f / c.Sc;
  c.kexp = -qv * c.Sinv * 1.4426950408889634f;   // Cc*exp(-q*s/S) == exp2(kexp*s + lCc)
  c.lCc  = log2f(Cc);
  c.sub  = clampf(pSUB[0], 0.f, 1.f);
  c.crak = clampf(pCRAK[0], 0.f, 1.f);
  c.rk   = clampf(pRecK[0] * 0.3f, 0.003f, 0.3f);
  c.lg   = clampf(pLG[0] * 0.1f, 0.001f, 0.1f);
  c.kr   = clampf(pKr[0] * 0.1f, 0.01f, 0.1f);
  c.ls   = clampf(pLS[0] * 10.f, 0.01f, 10.f);

  __shared__ float2 sbuf[2][CH][32];   // (U, BAS) per step per lane, double-buffered
  __shared__ float finS[32], finG[32];

  const float4* __restrict__ xin = xin_all + (size_t)seq * TT;
  float* __restrict__ op = out + (size_t)seq * TT;

  if (warp == 0) {
    // ================= producer: SMS + GW chains =================
    float S = 0.f, G = 0.f;
    float4 gb[8];
#pragma unroll
    for (int i = 0; i < 8; i++) gb[i] = xin[i];

    for (int ch = 0; ch < NCH; ++ch) {
      const int t0 = ch * CH;
      const int sl = ch & 1;
#pragma unroll
      for (int gi = 0; gi < CH / 8; ++gi) {
        float4 cur[8];
#pragma unroll
        for (int i = 0; i < 8; i++) cur[i] = gb[i];
        const int nxt = t0 + (gi + 1) * 8;
        if (nxt < TT) {
#pragma unroll
          for (int i = 0; i < 8; i++) gb[i] = xin[nxt + i];
        }
#pragma unroll
        for (int i = 0; i < 8; i++) {
          float Prec = cur[i].x, PET = cur[i].y;
          float INTC = fminf(fminf(c.insc, PET), Prec);
          float INR  = Prec - INTC;
          float POT  = PET  - INTC;
          float SMS1c = fminf(S, c.Sc);                  // >=0 invariant
          float infil = ex2_ap(fmaf(c.kexp, SMS1c, c.lCc));
          float ratio = SMS1c * c.Sinv;
          float sr  = c.sub  * ratio;
          float cr  = c.crak * ratio;
          float msr = 1.f - sr;
          float m   = msr * (1.f - cr);
          float mcr = cr * msr;
          float ETS  = fminf(POT, 10.f * ratio);
          float base = SMS1c - ETS;
          float w = fmaf(m, INR,   base);
          float z = fmaf(m, infil, base);
          float SMSn = fminf(w, z);                      // base + m*min(INR,infil)
          float RMO  = fminf(INR, infil);
          float U    = fmaf(-msr, RMO, INR);             // IRUN + SRUN
          float REC  = mcr * RMO;
          float RECn = REC + relu(SMSn - c.Sc);
          float BAS  = c.rk * relu(G);
          float GWn  = ((G - c.lg) + RECn) - BAS;
          sbuf[sl][gi * 8 + i][lane] = make_float2(U, BAS);
          S = SMSn; G = GWn;
        }
      }
      if (ch == NCH - 1) { finS[lane] = S; finG[lane] = G; }
      __syncthreads();
    }
    __syncthreads();   // matches consumer's trailing epoch
  } else {
    // ================= consumer: RS chain + fused pass-2 Q =================
    float R = 0.f, sqR = 0.f, rs0 = 0.f;
    float4 gb[8];
#pragma unroll
    for (int i = 0; i < 8; i++) gb[i] = xin[i];
    float4 first = gb[0];

    __syncthreads();   // wait for producer's chunk 0

    for (int ch = 0; ch < NCH; ++ch) {
      const int t0 = ch * CH;
      const int sl = ch & 1;
      float qb0 = 0.f, qb1 = 0.f, qb2 = 0.f;
#pragma unroll
      for (int gi = 0; gi < CH / 8; ++gi) {
        float4 cur[8];
#pragma unroll
        for (int i = 0; i < 8; i++) cur[i] = gb[i];
        const int nxt = t0 + (gi + 1) * 8;
        if (nxt < TT) {
#pragma unroll
          for (int i = 0; i < 8; i++) gb[i] = xin[nxt + i];
        }
#pragma unroll
        for (int i = 0; i < 8; i++) {
          float RSmax = cur[i].z, Area = cur[i].w;
          float2 ub = sbuf[sl][gi * 8 + i][lane];
          float U = ub.x, BAS = ub.y;

          float u    = rsq_ap(RSmax);
          float crs  = c.kr * (u * u * u);          // kr * RSmax^-1.5
          float krR  = c.kr * RSmax;
          float RSov = RSmax - krR;
          float onemA = 1.f - Area;

          float inflow = (U + BAS) * Area;
          float Rpi = R + inflow;
          float x5  = Rpi - RSmax;
          float t1  = (crs * sqR) * R;              // kr * R^1.5 / RSmax^1.5
          float RSn_no = fmaf(-t1, R, Rpi);
          float RSn = (x5 > 0.f) ? RSov : RSn_no;
          float sqn = sqrt_ap(RSn);

          float x6 = RSn + inflow - RSmax;
          float Qor2 = relu(x6);
          float Qir2 = (x6 > 0.f) ? krR : ((crs * RSn) * (RSn * sqn));
          float drarg = fmaf(U, onemA, (Qir2 + Qor2) - c.ls);
          float Q = relu(relu(drarg) + BAS * onemA);

          R = RSn; sqR = sqn;
          if (ch == 0 && gi == 0 && i == 0) rs0 = RSn;

          int ii = (gi * 8 + i) & 3;
          if      (ii == 0) qb0 = Q;
          else if (ii == 1) qb1 = Q;
          else if (ii == 2) qb2 = Q;
          else *reinterpret_cast<float4*>(op + t0 + gi * 8 + i - 3) =
                 make_float4(qb0, qb1, qb2, Q);
        }
      }
      __syncthreads();
    }

    // Q[b,0]: jnp.roll wrap -> SMS1/GW1 = FINAL states; RS = outs[b,0,2]
    op[0] = q_final(first, finS[lane], finG[lane], rs0, c);
  }
}

extern "C" void kernel_launch(void* const* d_in, const int* in_sizes, int n_in,
                              void* d_out, int out_size) {
  const float4* xin = (const float4*)d_in[0];
  int B = out_size / TT;
  int grid = B / 32;
  hirnn_kernel<<<grid, 64>>>(xin,
      (const float*)d_in[1], (const float*)d_in[2], (const float*)d_in[3],
      (const float*)d_in[4], (const float*)d_in[5], (const float*)d_in[6],
      (const float*)d_in[7], (const float*)d_in[8], (const float*)d_in[9],
      (const float*)d_in[10],
      (float*)d_out, B);
}

// round 10
// speedup vs baseline: 1.7473x; 1.3021x over previous
#include <cuda_runtime.h>
#include <cstdint>

#define TT 2048
#define CH 8
#define NCH (TT / CH)      // 256 chunks
#define PAD 33

__device__ __forceinline__ float ex2_ap (float x){ float r; asm("ex2.approx.f32 %0, %1;"   : "=f"(r) : "f"(x)); return r; }
__device__ __forceinline__ float rcp_ap (float x){ float r; asm("rcp.approx.f32 %0, %1;"   : "=f"(r) : "f"(x)); return r; }
__device__ __forceinline__ float sqrt_ap(float x){ float r; asm("sqrt.approx.f32 %0, %1;"  : "=f"(r) : "f"(x)); return r; }
__device__ __forceinline__ float rsq_ap (float x){ float r; asm("rsqrt.approx.f32 %0, %1;" : "=f"(r) : "f"(x)); return r; }
__device__ __forceinline__ float clampf(float x, float lo, float hi){ return fminf(fmaxf(x, lo), hi); }
__device__ __forceinline__ float relu(float x){ return fmaxf(x, 0.f); }

struct Consts {
  float insc, Sc, Sinv, kexp, lCc, sub, crak, rk, lg, kr, ls;
};

// Full pass-2 Q for t==0: rolled SMS/GW = FINAL states, RS = outs[b,0,2]
__device__ __forceinline__ float q_final(float4 v, float SMS1r, float GW1r, float RSr, const Consts& c)
{
  float Prec = v.x, PET = v.y, RSmax = v.z, Area = v.w;
  float INTC = fminf(fminf(c.insc, PET), Prec);
  float INR  = Prec - INTC;
  float SMS1c = fmaxf(fminf(SMS1r, c.Sc), 0.f);
  float infil = ex2_ap(fmaf(c.kexp, SMS1c, c.lCc));
  float RMO = fminf(INR, infil);
  float IRUN = INR - RMO;
  float ratio = SMS1c * c.Sinv;
  float SRUN = c.sub * ratio * RMO;
  float BAS = c.rk * relu(GW1r);
  float inflow = (IRUN + SRUN + BAS) * Area;
  float x5 = RSr + inflow - RSmax;
  float Qor = relu(x5);
  float r = relu(RSr) * rcp_ap(RSmax);
  float pw = r * sqrt_ap(r);
  float Qir = (x5 > 0.f) ? (c.kr * RSmax) : (c.kr * RSr * pw);
  float drarg = (SRUN + IRUN) * (1.f - Area) + Qir + Qor - c.ls;
  float DR = relu(drarg);
  float GD = BAS * (1.f - Area);
  return relu(DR + GD);
}

__global__ void __launch_bounds__(160, 1)
hirnn_kernel(const float4* __restrict__ xin_all,
             const float* __restrict__ pINSC, const float* __restrict__ pCOEFF,
             const float* __restrict__ pSQ,   const float* __restrict__ pSMSC,
             const float* __restrict__ pSUB,  const float* __restrict__ pCRAK,
             const float* __restrict__ pRecK, const float* __restrict__ pKr,
             const float* __restrict__ pLG,   const float* __restrict__ pLS,
             float* __restrict__ out, int B)
{
  const int lane = threadIdx.x & 31;
  const int warp = threadIdx.x >> 5;
  const int seq  = blockIdx.x * 32 + lane;

  Consts c;
  c.insc = clampf(pINSC[0] * 5.f, 0.5f, 5.f);
  float Cc = clampf(pCOEFF[0] * 400.f, 50.f, 400.f);
  float qv = clampf(pSQ[0] * 6.f, 0.f, 6.f);
  c.Sc   = clampf(pSMSC[0] * 500.f, 50.f, 500.f);
  c.Sinv = 1.f / c.Sc;
  c.kexp = -qv * c.Sinv * 1.4426950408889634f;   // Cc*exp(-q*s/S) == exp2(kexp*s + lCc)
  c.lCc  = log2f(Cc);
  c.sub  = clampf(pSUB[0], 0.f, 1.f);
  c.crak = clampf(pCRAK[0], 0.f, 1.f);
  c.rk   = clampf(pRecK[0] * 0.3f, 0.003f, 0.3f);
  c.lg   = clampf(pLG[0] * 0.1f, 0.001f, 0.1f);
  c.kr   = clampf(pKr[0] * 0.1f, 0.01f, 0.1f);
  c.ls   = clampf(pLS[0] * 10.f, 0.01f, 10.f);

  // inter-stage relay planes (slot count = stage distance to furthest consumer + 1)
  __shared__ float2 p0a[2][CH][PAD];   // W0 -> W1 (d=1): INR, POT
  __shared__ float2 p0b[4][CH][PAD];   // W0 -> W2,W3 (d=3): RSmax, Area
  __shared__ float2 p1 [3][CH][PAD];   // W1 -> W2,W3 (d=2): U, RECn
  __shared__ float4 p2 [2][CH][PAD];   // W2 -> W3 (d=1): BAS, crs, krR, RSov
  __shared__ float4 p3a[2][CH][PAD];   // W3 -> W4 (d=1): x6, krR, qno, U
  __shared__ float2 p3b[2][CH][PAD];   // W3 -> W4 (d=1): BAS, onemA
  __shared__ float fin1[32], fin2[32], rs0s[32];

  const float4* __restrict__ xin = xin_all + (size_t)seq * TT;
  float* __restrict__ op = out + (size_t)seq * TT;

  if (warp == 0) {
    // ---------- stage 0: load + interception (no recurrence) ----------
    float4 bA[CH], bB[CH];
#pragma unroll
    for (int i = 0; i < CH; i++) bA[i] = xin[i];
    for (int e = 0; e < NCH + 4; ++e) {
      if (e < NCH) {
        const int s1 = e & 1, s3 = e & 3;
        if ((e & 1) == 0) {
          if (e + 1 < NCH) {
#pragma unroll
            for (int i = 0; i < CH; i++) bB[i] = xin[(e + 1) * CH + i];
          }
#pragma unroll
          for (int i = 0; i < CH; i++) {
            float Prec = bA[i].x, PET = bA[i].y;
            float INTC = fminf(fminf(c.insc, PET), Prec);
            p0a[s1][i][lane] = make_float2(Prec - INTC, PET - INTC);
            p0b[s3][i][lane] = make_float2(bA[i].z, bA[i].w);
          }
        } else {
          if (e + 1 < NCH) {
#pragma unroll
            for (int i = 0; i < CH; i++) bA[i] = xin[(e + 1) * CH + i];
          }
#pragma unroll
          for (int i = 0; i < CH; i++) {
            float Prec = bB[i].x, PET = bB[i].y;
            float INTC = fminf(fminf(c.insc, PET), Prec);
            p0a[s1][i][lane] = make_float2(Prec - INTC, PET - INTC);
            p0b[s3][i][lane] = make_float2(bB[i].z, bB[i].w);
          }
        }
      }
      __syncthreads();
    }
  } else if (warp == 1) {
    // ---------- stage 1: SMS recurrence ----------
    float S = 0.f;
    for (int e = 0; e < NCH + 4; ++e) {
      const int k = e - 1;
      if (k >= 0 && k < NCH) {
        const int s0 = k & 1, sd = k % 3;
#pragma unroll
        for (int i = 0; i < CH; i++) {
          float2 io = p0a[s0][i][lane];
          float INR = io.x, POT = io.y;
          float SMS1c = fminf(S, c.Sc);                 // >=0 invariant
          float infil = ex2_ap(fmaf(c.kexp, SMS1c, c.lCc));
          float ratio = SMS1c * c.Sinv;
          float sr  = c.sub  * ratio;
          float cr  = c.crak * ratio;
          float msr = 1.f - sr;
          float m   = msr * (1.f - cr);
          float mcr = cr * msr;
          float ETS  = fminf(POT, 10.f * ratio);
          float base = SMS1c - ETS;
          float w = fmaf(m, INR,   base);
          float z = fmaf(m, infil, base);
          float SMSn = fminf(w, z);                     // base + m*min(INR,infil)
          float RMO  = fminf(INR, infil);
          float U    = fmaf(-msr, RMO, INR);            // IRUN + SRUN
          float RECn = fmaf(mcr, RMO, relu(SMSn - c.Sc));  // REC + relu(xr)
          p1[sd][i][lane] = make_float2(U, RECn);
          S = SMSn;
        }
        if (k == NCH - 1) fin1[lane] = S;
      }
      __syncthreads();
    }
  } else if (warp == 2) {
    // ---------- stage 2: GW recurrence + RSmax-derived constants ----------
    float G = 0.f;
    for (int e = 0; e < NCH + 4; ++e) {
      const int k = e - 2;
      if (k >= 0 && k < NCH) {
        const int s0 = k & 3, s1 = k % 3, s2 = k & 1;
#pragma unroll
        for (int i = 0; i < CH; i++) {
          float RSmax = p0b[s0][i][lane].x;
          float RECn  = p1[s1][i][lane].y;
          float u   = rsq_ap(RSmax);
          float crs = c.kr * ((u * u) * u);     // kr * RSmax^-1.5
          float krR = c.kr * RSmax;
          float RSov = RSmax - krR;
          float BAS = c.rk * relu(G);
          float GWn = ((G - c.lg) + RECn) - BAS;
          p2[s2][i][lane] = make_float4(BAS, crs, krR, RSov);
          G = GWn;
        }
        if (k == NCH - 1) fin2[lane] = G;
      }
      __syncthreads();
    }
  } else if (warp == 3) {
    // ---------- stage 3: RS recurrence ----------
    float R = 0.f, sqR = 0.f;
    for (int e = 0; e < NCH + 4; ++e) {
      const int k = e - 3;
      if (k >= 0 && k < NCH) {
        const int s0 = k & 3, s1 = k % 3, s2 = k & 1;
#pragma unroll
        for (int i = 0; i < CH; i++) {
          float2 ra = p0b[s0][i][lane];          // RSmax, Area
          float U   = p1[s1][i][lane].x;
          float4 q  = p2[s2][i][lane];           // BAS, crs, krR, RSov
          float inflow = (U + q.x) * ra.y;
          float Rpi = R + inflow;
          float x5  = Rpi - ra.x;
          float t1  = (q.y * sqR) * R;           // kr * R^1.5 / RSmax^1.5
          float RSn_no = fmaf(-t1, R, Rpi);
          float RSn = (x5 > 0.f) ? q.w : RSn_no;
          float sqn = sqrt_ap(RSn);
          float x6  = (RSn + inflow) - ra.x;
          float qno = (q.y * RSn) * (RSn * sqn); // kr*RSn*(RSn/RSmax)^1.5
          p3a[s2][i][lane] = make_float4(x6, q.z, qno, U);
          p3b[s2][i][lane] = make_float2(q.x, 1.f - ra.y);
          if (k == 0 && i == 0) rs0s[lane] = RSn;
          R = RSn; sqR = sqn;
        }
      }
      __syncthreads();
    }
  } else {
    // ---------- stage 4: Q tail + stores ----------
    for (int e = 0; e < NCH + 4; ++e) {
      const int k = e - 4;
      if (k >= 0 && k < NCH) {
        const int s = k & 1;
        float qb0 = 0.f, qb1 = 0.f, qb2 = 0.f;
#pragma unroll
        for (int i = 0; i < CH; i++) {
          float4 a = p3a[s][i][lane];            // x6, krR, qno, U
          float2 b = p3b[s][i][lane];            // BAS, onemA
          float Qor2 = relu(a.x);
          float Qir2 = (a.x > 0.f) ? a.y : a.z;
          float ssum = (Qir2 + Qor2) - c.ls;
          float drarg = fmaf(a.w, b.y, ssum);
          float Q = relu(relu(drarg) + b.x * b.y);
          int ii = i & 3;
          if      (ii == 0) qb0 = Q;
          else if (ii == 1) qb1 = Q;
          else if (ii == 2) qb2 = Q;
          else *reinterpret_cast<float4*>(op + k * CH + i - 3) =
                 make_float4(qb0, qb1, qb2, Q);
        }
      }
      __syncthreads();
    }
    // Q[b,0]: jnp.roll wrap -> SMS1/GW1 = FINAL states; RS = outs[b,0,2]
    float4 f = xin[0];
    op[0] = q_final(f, fin1[lane], fin2[lane], rs0s[lane], c);
  }
}

extern "C" void kernel_launch(void* const* d_in, const int* in_sizes, int n_in,
                              void* d_out, int out_size) {
  const float4* xin = (const float4*)d_in[0];
  int B = out_size / TT;
  int grid = B / 32;
  hirnn_kernel<<<grid, 160>>>(xin,
      (const float*)d_in[1], (const float*)d_in[2], (const float*)d_in[3],
      (const float*)d_in[4], (const float*)d_in[5], (const float*)d_in[6],
      (const float*)d_in[7], (const float*)d_in[8], (const float*)d_in[9],
      (const float*)d_in[10],
      (float*)d_out, B);
}

// round 11
// speedup vs baseline: 2.2143x; 1.2673x over previous
#include <cuda_runtime.h>
#include <cstdint>

#define TT 2048
#define CH 16
#define NCH (TT / CH)      // 128 chunks
#define PAD 33

__device__ __forceinline__ float ex2_ap (float x){ float r; asm("ex2.approx.f32 %0, %1;"   : "=f"(r) : "f"(x)); return r; }
__device__ __forceinline__ float rcp_ap (float x){ float r; asm("rcp.approx.f32 %0, %1;"   : "=f"(r) : "f"(x)); return r; }
__device__ __forceinline__ float sqrt_ap(float x){ float r; asm("sqrt.approx.f32 %0, %1;"  : "=f"(r) : "f"(x)); return r; }
__device__ __forceinline__ float rsq_ap (float x){ float r; asm("rsqrt.approx.f32 %0, %1;" : "=f"(r) : "f"(x)); return r; }
__device__ __forceinline__ float clampf(float x, float lo, float hi){ return fminf(fmaxf(x, lo), hi); }
__device__ __forceinline__ float relu(float x){ return fmaxf(x, 0.f); }

// dynamic smem layout (bytes)
#define SZ_P2   (2 * CH * PAD * 16)
#define SZ_P3A  (2 * CH * PAD * 16)
#define SZ_P0A  (2 * CH * PAD * 8)
#define SZ_P0B  (4 * CH * PAD * 8)
#define SZ_P1   (3 * CH * PAD * 8)
#define SZ_P3B  (2 * CH * PAD * 8)
#define OFF_P2   0
#define OFF_P3A  (OFF_P2  + SZ_P2)
#define OFF_P0A  (OFF_P3A + SZ_P3A)
#define OFF_P0B  (OFF_P0A + SZ_P0A)
#define OFF_P1   (OFF_P0B + SZ_P0B)
#define OFF_P3B  (OFF_P1  + SZ_P1)
#define OFF_FIN1 (OFF_P3B + SZ_P3B)
#define OFF_FIN2 (OFF_FIN1 + 128)
#define OFF_RS0  (OFF_FIN2 + 128)
#define SMEM_TOTAL (OFF_RS0 + 128)

struct Consts {
  float insc, Sc, Sinv, kexp, lCc, sub, crak, rk, lg, kr, ls;
};

// Full pass-2 Q for t==0: rolled SMS/GW = FINAL states, RS = outs[b,0,2]
__device__ __forceinline__ float q_final(float4 v, float SMS1r, float GW1r, float RSr, const Consts& c)
{
  float Prec = v.x, PET = v.y, RSmax = v.z, Area = v.w;
  float INTC = fminf(fminf(c.insc, PET), Prec);
  float INR  = Prec - INTC;
  float SMS1c = fmaxf(fminf(SMS1r, c.Sc), 0.f);
  float infil = ex2_ap(fmaf(c.kexp, SMS1c, c.lCc));
  float RMO = fminf(INR, infil);
  float IRUN = INR - RMO;
  float ratio = SMS1c * c.Sinv;
  float SRUN = c.sub * ratio * RMO;
  float BAS = c.rk * relu(GW1r);
  float inflow = (IRUN + SRUN + BAS) * Area;
  float x5 = RSr + inflow - RSmax;
  float Qor = relu(x5);
  float r = relu(RSr) * rcp_ap(RSmax);
  float pw = r * sqrt_ap(r);
  float Qir = (x5 > 0.f) ? (c.kr * RSmax) : (c.kr * RSr * pw);
  float drarg = (SRUN + IRUN) * (1.f - Area) + Qir + Qor - c.ls;
  float DR = relu(drarg);
  float GD = BAS * (1.f - Area);
  return relu(DR + GD);
}

__global__ void __launch_bounds__(160, 1)
hirnn_kernel(const float4* __restrict__ xin_all,
             const float* __restrict__ pINSC, const float* __restrict__ pCOEFF,
             const float* __restrict__ pSQ,   const float* __restrict__ pSMSC,
             const float* __restrict__ pSUB,  const float* __restrict__ pCRAK,
             const float* __restrict__ pRecK, const float* __restrict__ pKr,
             const float* __restrict__ pLG,   const float* __restrict__ pLS,
             float* __restrict__ out, int B)
{
  const int lane = threadIdx.x & 31;
  const int warp = threadIdx.x >> 5;
  const int seq  = blockIdx.x * 32 + lane;

  extern __shared__ unsigned char dyn[];
  typedef float2 P2CH[CH][PAD];
  typedef float4 P4CH[CH][PAD];
  P4CH* p2  = (P4CH*)(dyn + OFF_P2);    // [2]: BAS, crs, krR, RSov
  P4CH* p3a = (P4CH*)(dyn + OFF_P3A);   // [2]: x6, krR, qno, U
  P2CH* p0a = (P2CH*)(dyn + OFF_P0A);   // [2]: INR, POT
  P2CH* p0b = (P2CH*)(dyn + OFF_P0B);   // [4]: RSmax, Area
  P2CH* p1  = (P2CH*)(dyn + OFF_P1);    // [3]: U, RECn
  P2CH* p3b = (P2CH*)(dyn + OFF_P3B);   // [2]: BAS, onemA
  float* fin1 = (float*)(dyn + OFF_FIN1);
  float* fin2 = (float*)(dyn + OFF_FIN2);
  float* rs0s = (float*)(dyn + OFF_RS0);

  Consts c;
  c.insc = clampf(pINSC[0] * 5.f, 0.5f, 5.f);
  float Cc = clampf(pCOEFF[0] * 400.f, 50.f, 400.f);
  float qv = clampf(pSQ[0] * 6.f, 0.f, 6.f);
  c.Sc   = clampf(pSMSC[0] * 500.f, 50.f, 500.f);
  c.Sinv = 1.f / c.Sc;
  c.kexp = -qv * c.Sinv * 1.4426950408889634f;   // Cc*exp(-q*s/S) == exp2(kexp*s + lCc)
  c.lCc  = log2f(Cc);
  c.sub  = clampf(pSUB[0], 0.f, 1.f);
  c.crak = clampf(pCRAK[0], 0.f, 1.f);
  c.rk   = clampf(pRecK[0] * 0.3f, 0.003f, 0.3f);
  c.lg   = clampf(pLG[0] * 0.1f, 0.001f, 0.1f);
  c.kr   = clampf(pKr[0] * 0.1f, 0.01f, 0.1f);
  c.ls   = clampf(pLS[0] * 10.f, 0.01f, 10.f);

  const float4* __restrict__ xin = xin_all + (size_t)seq * TT;
  float* __restrict__ op = out + (size_t)seq * TT;

  if (warp == 0) {
    // ---------- stage 0: load + interception (no recurrence) ----------
    float4 bA[CH], bB[CH];
#pragma unroll
    for (int i = 0; i < CH; i++) bA[i] = xin[i];
    for (int e = 0; e < NCH + 4; ++e) {
      if (e < NCH) {
        const int s1 = e & 1, s3 = e & 3;
        if ((e & 1) == 0) {
          if (e + 1 < NCH) {
#pragma unroll
            for (int i = 0; i < CH; i++) bB[i] = xin[(e + 1) * CH + i];
          }
#pragma unroll
          for (int i = 0; i < CH; i++) {
            float Prec = bA[i].x, PET = bA[i].y;
            float INTC = fminf(fminf(c.insc, PET), Prec);
            p0a[s1][i][lane] = make_float2(Prec - INTC, PET - INTC);
            p0b[s3][i][lane] = make_float2(bA[i].z, bA[i].w);
          }
        } else {
          if (e + 1 < NCH) {
#pragma unroll
            for (int i = 0; i < CH; i++) bA[i] = xin[(e + 1) * CH + i];
          }
#pragma unroll
          for (int i = 0; i < CH; i++) {
            float Prec = bB[i].x, PET = bB[i].y;
            float INTC = fminf(fminf(c.insc, PET), Prec);
            p0a[s1][i][lane] = make_float2(Prec - INTC, PET - INTC);
            p0b[s3][i][lane] = make_float2(bB[i].z, bB[i].w);
          }
        }
      }
      __syncthreads();
    }
  } else if (warp == 1) {
    // ---------- stage 1: SMS recurrence ----------
    float S = 0.f;
    for (int e = 0; e < NCH + 4; ++e) {
      const int k = e - 1;
      if (k >= 0 && k < NCH) {
        const int s0 = k & 1, sd = k % 3;
#pragma unroll
        for (int i = 0; i < CH; i++) {
          float2 io = p0a[s0][i][lane];
          float INR = io.x, POT = io.y;
          float SMS1c = fminf(S, c.Sc);                 // >=0 invariant
          float infil = ex2_ap(fmaf(c.kexp, SMS1c, c.lCc));
          float ratio = SMS1c * c.Sinv;
          float sr  = c.sub  * ratio;
          float cr  = c.crak * ratio;
          float msr = 1.f - sr;
          float m   = msr * (1.f - cr);
          float mcr = cr * msr;
          float ETS  = fminf(POT, 10.f * ratio);
          float base = SMS1c - ETS;
          float w = fmaf(m, INR,   base);
          float z = fmaf(m, infil, base);
          float SMSn = fminf(w, z);                     // base + m*min(INR,infil)
          float RMO  = fminf(INR, infil);
          float U    = fmaf(-msr, RMO, INR);            // IRUN + SRUN
          float RECn = fmaf(mcr, RMO, relu(SMSn - c.Sc));  // REC + relu(xr)
          p1[sd][i][lane] = make_float2(U, RECn);
          S = SMSn;
        }
        if (k == NCH - 1) fin1[lane] = S;
      }
      __syncthreads();
    }
  } else if (warp == 2) {
    // ---------- stage 2: GW recurrence + RSmax-derived constants ----------
    float G = 0.f;
    for (int e = 0; e < NCH + 4; ++e) {
      const int k = e - 2;
      if (k >= 0 && k < NCH) {
        const int s0 = k & 3, s1 = k % 3, s2 = k & 1;
#pragma unroll
        for (int i = 0; i < CH; i++) {
          float RSmax = p0b[s0][i][lane].x;
          float RECn  = p1[s1][i][lane].y;
          float u   = rsq_ap(RSmax);
          float crs = c.kr * ((u * u) * u);     // kr * RSmax^-1.5
          float krR = c.kr * RSmax;
          float RSov = RSmax - krR;
          float BAS = c.rk * relu(G);
          float GWn = ((G - c.lg) + RECn) - BAS;
          p2[s2][i][lane] = make_float4(BAS, crs, krR, RSov);
          G = GWn;
        }
        if (k == NCH - 1) fin2[lane] = G;
      }
      __syncthreads();
    }
  } else if (warp == 3) {
    // ---------- stage 3: RS recurrence ----------
    float R = 0.f, sqR = 0.f;
    for (int e = 0; e < NCH + 4; ++e) {
      const int k = e - 3;
      if (k >= 0 && k < NCH) {
        const int s0 = k & 3, s1 = k % 3, s2 = k & 1;
#pragma unroll
        for (int i = 0; i < CH; i++) {
          float2 ra = p0b[s0][i][lane];          // RSmax, Area
          float U   = p1[s1][i][lane].x;
          float4 q  = p2[s2][i][lane];           // BAS, crs, krR, RSov
          float inflow = (U + q.x) * ra.y;
          float Rpi = R + inflow;
          float x5  = Rpi - ra.x;
          float t1  = (q.y * sqR) * R;           // kr * R^1.5 / RSmax^1.5
          float RSn_no = fmaf(-t1, R, Rpi);
          float RSn = (x5 > 0.f) ? q.w : RSn_no;
          float sqn = sqrt_ap(RSn);
          float x6  = (RSn + inflow) - ra.x;
          float qno = (q.y * RSn) * (RSn * sqn); // kr*RSn*(RSn/RSmax)^1.5
          p3a[s2][i][lane] = make_float4(x6, q.z, qno, U);
          p3b[s2][i][lane] = make_float2(q.x, 1.f - ra.y);
          if (k == 0 && i == 0) rs0s[lane] = RSn;
          R = RSn; sqR = sqn;
        }
      }
      __syncthreads();
    }
  } else {
    // ---------- stage 4: Q tail + stores ----------
    for (int e = 0; e < NCH + 4; ++e) {
      const int k = e - 4;
      if (k >= 0 && k < NCH) {
        const int s = k & 1;
        float qb0 = 0.f, qb1 = 0.f, qb2 = 0.f;
#pragma unroll
        for (int i = 0; i < CH; i++) {
          float4 a = p3a[s][i][lane];            // x6, krR, qno, U
          float2 b = p3b[s][i][lane];            // BAS, onemA
          float Qor2 = relu(a.x);
          float Qir2 = (a.x > 0.f) ? a.y : a.z;
          float ssum = (Qir2 + Qor2) - c.ls;
          float drarg = fmaf(a.w, b.y, ssum);
          float Q = relu(relu(drarg) + b.x * b.y);
          int ii = i & 3;
          if      (ii == 0) qb0 = Q;
          else if (ii == 1) qb1 = Q;
          else if (ii == 2) qb2 = Q;
          else *reinterpret_cast<float4*>(op + k * CH + i - 3) =
                 make_float4(qb0, qb1, qb2, Q);
        }
      }
      __syncthreads();
    }
    // Q[b,0]: jnp.roll wrap -> SMS1/GW1 = FINAL states; RS = outs[b,0,2]
    float4 f = xin[0];
    op[0] = q_final(f, fin1[lane], fin2[lane], rs0s[lane], c);
  }
}

extern "C" void kernel_launch(void* const* d_in, const int* in_sizes, int n_in,
                              void* d_out, int out_size) {
  const float4* xin = (const float4*)d_in[0];
  int B = out_size / TT;
  int grid = B / 32;
  static int attr_set = 0;
  if (!attr_set) {
    cudaFuncSetAttribute(hirnn_kernel, cudaFuncAttributeMaxDynamicSharedMemorySize, SMEM_TOTAL);
    attr_set = 1;
  }
  hirnn_kernel<<<grid, 160, SMEM_TOTAL>>>(xin,
      (const float*)d_in[1], (const float*)d_in[2], (const float*)d_in[3],
      (const float*)d_in[4], (const float*)d_in[5], (const float*)d_in[6],
      (const float*)d_in[7], (const float*)d_in[8], (const float*)d_in[9],
      (const float*)d_in[10],
      (float*)d_out, B);
}